// round 1
// baseline (speedup 1.0000x reference)
#include <cuda_runtime.h>
#include <cuda_bf16.h>

// Problem constants
#define Bn   256
#define Cn   512
#define Nn   49          // 7x7 attention positions
#define HWn  196         // 14*14
#define Mrows (Bn*Nn)    // 12544

// Scratch (no allocation allowed)
__device__ float g_a[Mrows * Cn];        // pooled, layout [B*N, C]
__device__ float g_ah[Bn * Cn];          // h@Wh^T + bh + ba
__device__ float g_spart[4 * Mrows];     // per-column-tile score partials

__device__ __forceinline__ float fast_tanh(float x) {
    float y;
    asm("tanh.approx.f32 %0, %1;" : "=f"(y) : "f"(x));
    return y;
}

// ---------------------------------------------------------------------------
// K1: 2x2 avg pool of att_v [B,C,14,14] -> a [B*49, C] (transpose via smem)
// grid (16 c-tiles, 256 b), 256 threads
// ---------------------------------------------------------------------------
__global__ __launch_bounds__(256) void pool_kernel(const float* __restrict__ att_v) {
    int b  = blockIdx.y;
    int c0 = blockIdx.x * 32;
    __shared__ float pool[32][51];      // pitch 51 -> conflict-free transpose read
    const float* base = att_v + ((size_t)b * Cn + c0) * HWn;
    int tid = threadIdx.x;

    for (int idx = tid; idx < 32 * Nn; idx += 256) {
        int cl = idx / Nn, n = idx % Nn;
        int i = n / 7, j = n % 7;
        const float* p = base + cl * HWn + i * 28 + j * 2;
        float2 t = *(const float2*)p;
        float2 u = *(const float2*)(p + 14);
        pool[cl][n] = (t.x + t.y + u.x + u.y) * 0.25f;
    }
    __syncthreads();
    for (int idx = tid; idx < 32 * Nn; idx += 256) {
        int n = idx / 32, cl = idx % 32;   // 49*32 = 1568 exactly
        g_a[(size_t)(b * Nn + n) * Cn + c0 + cl] = pool[cl][n];
    }
}

// ---------------------------------------------------------------------------
// K2: g_ah[b,d] = sum_c h[b,c]*Wh[d,c] + bh[d] + ba[d]
// grid (32 d-tiles, 16 b-tiles), 256 threads (16x16)
// ---------------------------------------------------------------------------
__global__ __launch_bounds__(256) void h2a_kernel(const float* __restrict__ h,
                                                  const float* __restrict__ Wh,
                                                  const float* __restrict__ bh,
                                                  const float* __restrict__ ba) {
    __shared__ float sh[16][132];
    __shared__ float sw[16][132];
    int tid = threadIdx.x;
    int tx = tid & 15, ty = tid >> 4;
    int d0 = blockIdx.x * 16, b0 = blockIdx.y * 16;
    float acc = 0.f;

    for (int c0 = 0; c0 < Cn; c0 += 128) {
#pragma unroll
        for (int p = 0; p < 2; ++p) {
            int i = tid + p * 256;       // 0..511
            int r = i >> 5;              // 0..15
            int cc = (i & 31) * 4;       // 0..124
            *(float4*)&sh[r][cc] = *(const float4*)&h [(size_t)(b0 + r) * Cn + c0 + cc];
            *(float4*)&sw[r][cc] = *(const float4*)&Wh[(size_t)(d0 + r) * Cn + c0 + cc];
        }
        __syncthreads();
#pragma unroll
        for (int c = 0; c < 128; ++c) acc += sh[ty][c] * sw[tx][c];
        __syncthreads();
    }
    int d = d0 + tx, b = b0 + ty;
    g_ah[(size_t)b * Cn + d] = acc + bh[d] + ba[d];
}

// ---------------------------------------------------------------------------
// K3: fused GEMM(M=12544,N=512,K=512) + tanh + dot(Wd) -> score partials
// BM=BN=128, BK=32, 256 threads, 8x8 per thread as 2x2 groups of 4x4.
// grid (4 col-tiles, 98 row-tiles)
// ---------------------------------------------------------------------------
__global__ __launch_bounds__(256) void gemm_score_kernel(const float* __restrict__ Wa,
                                                         const float* __restrict__ Wd) {
    __shared__ float As[128][36];    // row-major, pitch 36: STS.128 conflict-free
    __shared__ float Bs[32][132];    // k-major, pitch 132: LDS.128 conflict-free

    int tid = threadIdx.x;
    int tx = tid & 15, ty = tid >> 4;
    int rowBase = blockIdx.y * 128;
    int colBase = blockIdx.x * 128;

    float acc[8][8];
#pragma unroll
    for (int i = 0; i < 8; ++i)
#pragma unroll
        for (int j = 0; j < 8; ++j) acc[i][j] = 0.f;

    int lr = tid >> 3;            // 0..31
    int lk = (tid & 7) * 4;       // 0,4,...,28

    for (int k0 = 0; k0 < Cn; k0 += 32) {
#pragma unroll
        for (int p = 0; p < 4; ++p) {
            int r = lr + p * 32;
            float4 va = *(const float4*)&g_a[(size_t)(rowBase + r) * Cn + k0 + lk];
            *(float4*)&As[r][lk] = va;
            float4 vb = *(const float4*)&Wa[(size_t)(colBase + r) * Cn + k0 + lk];
            Bs[lk + 0][r] = vb.x; Bs[lk + 1][r] = vb.y;
            Bs[lk + 2][r] = vb.z; Bs[lk + 3][r] = vb.w;
        }
        __syncthreads();
#pragma unroll
        for (int k = 0; k < 32; ++k) {
            float af[8], bf[8];
#pragma unroll
            for (int i = 0; i < 4; ++i) {
                af[i]     = As[ty * 4 + i][k];        // broadcast within half-warp
                af[4 + i] = As[64 + ty * 4 + i][k];
            }
            float4 b0 = *(const float4*)&Bs[k][tx * 4];
            float4 b1 = *(const float4*)&Bs[k][64 + tx * 4];
            bf[0] = b0.x; bf[1] = b0.y; bf[2] = b0.z; bf[3] = b0.w;
            bf[4] = b1.x; bf[5] = b1.y; bf[6] = b1.z; bf[7] = b1.w;
#pragma unroll
            for (int i = 0; i < 8; ++i)
#pragma unroll
                for (int j = 0; j < 8; ++j)
                    acc[i][j] += af[i] * bf[j];
        }
        __syncthreads();
    }

    // Epilogue: tanh(av + ah) . Wd  -> per-row partial over this col tile
    int cA = colBase + tx * 4;
    int cB = colBase + 64 + tx * 4;
    float wd[8];
#pragma unroll
    for (int j = 0; j < 4; ++j) { wd[j] = Wd[cA + j]; wd[4 + j] = Wd[cB + j]; }

    float partial[8];
#pragma unroll
    for (int i = 0; i < 8; ++i) {
        int row = rowBase + ((i < 4) ? (ty * 4 + i) : (64 + ty * 4 + (i - 4)));
        int b = row / Nn;
        const float* ahr = g_ah + (size_t)b * Cn;
        float s = 0.f;
#pragma unroll
        for (int j = 0; j < 8; ++j) {
            int col = (j < 4) ? (cA + j) : (cB + (j - 4));
            s += fast_tanh(acc[i][j] + ahr[col]) * wd[j];
        }
        partial[i] = s;
    }
    // reduce across the 16 threads (tx) sharing the same rows; width-16 segments
#pragma unroll
    for (int off = 8; off > 0; off >>= 1)
#pragma unroll
        for (int i = 0; i < 8; ++i)
            partial[i] += __shfl_down_sync(0xffffffffu, partial[i], off, 16);

    if (tx == 0) {
#pragma unroll
        for (int i = 0; i < 8; ++i) {
            int row = rowBase + ((i < 4) ? (ty * 4 + i) : (64 + ty * 4 + (i - 4)));
            g_spart[blockIdx.x * Mrows + row] = partial[i];
        }
    }
}

// ---------------------------------------------------------------------------
// K4: scores = sum(partials) + bd; softmax over 49; out[b,c] = sum_n a*w
// grid 256 (one per b), 256 threads
// ---------------------------------------------------------------------------
__global__ __launch_bounds__(256) void softmax_out_kernel(const float* __restrict__ bd,
                                                          float* __restrict__ out) {
    int b = blockIdx.x;
    int tid = threadIdx.x;
    __shared__ float w[Nn];
    __shared__ float sinv;

    if (tid < Nn) {
        float s = bd[0];
#pragma unroll
        for (int i = 0; i < 4; ++i) s += g_spart[i * Mrows + b * Nn + tid];
        w[tid] = s;
    }
    __syncthreads();
    if (tid == 0) {
        float m = -1e30f;
        for (int n = 0; n < Nn; ++n) m = fmaxf(m, w[n]);
        float sum = 0.f;
        for (int n = 0; n < Nn; ++n) { float e = __expf(w[n] - m); w[n] = e; sum += e; }
        sinv = 1.0f / sum;
    }
    __syncthreads();
    float inv = sinv;

    const float* ab = g_a + (size_t)b * Nn * Cn;
    for (int c = tid; c < Cn; c += 256) {
        float acc = 0.f;
#pragma unroll
        for (int n = 0; n < Nn; ++n) acc += ab[n * Cn + c] * w[n];
        out[b * Cn + c] = acc * inv;
    }
}

// ---------------------------------------------------------------------------
extern "C" void kernel_launch(void* const* d_in, const int* in_sizes, int n_in,
                              void* d_out, int out_size) {
    const float* att_v = (const float*)d_in[0];
    const float* h     = (const float*)d_in[1];
    const float* Wa    = (const float*)d_in[2];
    const float* ba    = (const float*)d_in[3];
    const float* Wh    = (const float*)d_in[4];
    const float* bh    = (const float*)d_in[5];
    const float* Wd    = (const float*)d_in[6];
    const float* bd    = (const float*)d_in[7];
    float* out = (float*)d_out;

    pool_kernel      <<<dim3(16, 256), 256>>>(att_v);
    h2a_kernel       <<<dim3(32, 16),  256>>>(h, Wh, bh, ba);
    gemm_score_kernel<<<dim3(4, 98),   256>>>(Wa, Wd);
    softmax_out_kernel<<<256, 256>>>(bd, out);
}

// round 2
// speedup vs baseline: 2.0537x; 2.0537x over previous
#include <cuda_runtime.h>
#include <cuda_bf16.h>
#include <cstdint>

// Problem constants
#define Bn   256
#define Cn   512
#define Nn   49          // 7x7 attention positions
#define HWn  196         // 14*14
#define Mrows (Bn*Nn)    // 12544

// Scratch (no allocation allowed)
__device__ float g_a[Mrows * Cn];        // pooled, layout [B*N, C]
__device__ float g_ah[Bn * Cn];          // h@Wh^T + bh + ba
__device__ float g_spart[8 * Mrows];     // per (col-tile, warp-col) score partials

__device__ __forceinline__ float fast_tanh(float x) {
    float y;
    asm("tanh.approx.f32 %0, %1;" : "=f"(y) : "f"(x));
    return y;
}
__device__ __forceinline__ uint32_t f2tf(float x) {
    uint32_t u;
    asm("cvt.rna.tf32.f32 %0, %1;" : "=r"(u) : "f"(x));
    return u;
}
__device__ __forceinline__ void mma_tf32(float* d, const uint32_t* a, const uint32_t* b) {
    asm volatile(
        "mma.sync.aligned.m16n8k8.row.col.f32.tf32.tf32.f32 "
        "{%0,%1,%2,%3}, {%4,%5,%6,%7}, {%8,%9}, {%0,%1,%2,%3};"
        : "+f"(d[0]), "+f"(d[1]), "+f"(d[2]), "+f"(d[3])
        : "r"(a[0]), "r"(a[1]), "r"(a[2]), "r"(a[3]), "r"(b[0]), "r"(b[1]));
}

// ---------------------------------------------------------------------------
// K1: 2x2 avg pool of att_v [B,C,14,14] -> a [B*49, C] (transpose via smem)
// ---------------------------------------------------------------------------
__global__ __launch_bounds__(256) void pool_kernel(const float* __restrict__ att_v) {
    int b  = blockIdx.y;
    int c0 = blockIdx.x * 32;
    __shared__ float pool[32][51];
    const float* base = att_v + ((size_t)b * Cn + c0) * HWn;
    int tid = threadIdx.x;

    for (int idx = tid; idx < 32 * Nn; idx += 256) {
        int cl = idx / Nn, n = idx % Nn;
        int i = n / 7, j = n % 7;
        const float* p = base + cl * HWn + i * 28 + j * 2;
        float2 t = *(const float2*)p;
        float2 u = *(const float2*)(p + 14);
        pool[cl][n] = (t.x + t.y + u.x + u.y) * 0.25f;
    }
    __syncthreads();
    for (int idx = tid; idx < 32 * Nn; idx += 256) {
        int n = idx / 32, cl = idx % 32;
        g_a[(size_t)(b * Nn + n) * Cn + c0 + cl] = pool[cl][n];
    }
}

// ---------------------------------------------------------------------------
// K2: g_ah[b,d] = sum_c h[b,c]*Wh[d,c] + bh[d] + ba[d]
// ---------------------------------------------------------------------------
__global__ __launch_bounds__(256) void h2a_kernel(const float* __restrict__ h,
                                                  const float* __restrict__ Wh,
                                                  const float* __restrict__ bh,
                                                  const float* __restrict__ ba) {
    __shared__ float sh[16][132];
    __shared__ float sw[16][132];
    int tid = threadIdx.x;
    int tx = tid & 15, ty = tid >> 4;
    int d0 = blockIdx.x * 16, b0 = blockIdx.y * 16;
    float acc = 0.f;

    for (int c0 = 0; c0 < Cn; c0 += 128) {
#pragma unroll
        for (int p = 0; p < 2; ++p) {
            int i = tid + p * 256;
            int r = i >> 5;
            int cc = (i & 31) * 4;
            *(float4*)&sh[r][cc] = *(const float4*)&h [(size_t)(b0 + r) * Cn + c0 + cc];
            *(float4*)&sw[r][cc] = *(const float4*)&Wh[(size_t)(d0 + r) * Cn + c0 + cc];
        }
        __syncthreads();
#pragma unroll
        for (int c = 0; c < 128; ++c) acc += sh[ty][c] * sw[tx][c];
        __syncthreads();
    }
    int d = d0 + tx, b = b0 + ty;
    g_ah[(size_t)b * Cn + d] = acc + bh[d] + ba[d];
}

// ---------------------------------------------------------------------------
// K3: fused tf32 tensor-core GEMM(M=12544,N=512,K=512) + tanh + dot(Wd)
// BM=BN=128, BK=32; 8 warps as 4(M) x 2(N); warp tile 32x64 via m16n8k8.
// grid (4 col-tiles, 98 row-tiles)
// ---------------------------------------------------------------------------
__global__ __launch_bounds__(256, 2) void gemm_score_kernel(const float* __restrict__ Wa,
                                                            const float* __restrict__ Wd) {
    __shared__ uint32_t As[128][36];   // [m][k] tf32 bits; pitch 36 -> conflict-free
    __shared__ uint32_t Bs[128][36];   // [n][k] tf32 bits
    __shared__ float    sAh[4][128];   // ah tile for the <=4 batches this row-tile spans
    __shared__ float    sWd[128];

    int tid  = threadIdx.x;
    int lane = tid & 31;
    int warp = tid >> 5;
    int warpM = warp & 3;              // 0..3  (32 rows each)
    int warpC = warp >> 2;             // 0..1  (64 cols each)
    int rowBase = blockIdx.y * 128;
    int colBase = blockIdx.x * 128;
    int b0 = rowBase / Nn;

    // stage ah tile + Wd tile
    for (int i = tid; i < 4 * 128; i += 256) {
        int bb = i >> 7, c = i & 127;
        int b = b0 + bb;
        sAh[bb][c] = (b < Bn) ? g_ah[(size_t)b * Cn + colBase + c] : 0.f;
    }
    if (tid < 128) sWd[tid] = Wd[colBase + tid];

    float acc[2][8][4];
#pragma unroll
    for (int mi = 0; mi < 2; ++mi)
#pragma unroll
        for (int ni = 0; ni < 8; ++ni)
#pragma unroll
            for (int q = 0; q < 4; ++q) acc[mi][ni][q] = 0.f;

    int lr = tid >> 3;              // 0..31
    int lc = (tid & 7) * 4;         // 0,4,...,28

    for (int k0 = 0; k0 < Cn; k0 += 32) {
#pragma unroll
        for (int p = 0; p < 4; ++p) {
            int r = lr + p * 32;
            float4 va = *(const float4*)&g_a[(size_t)(rowBase + r) * Cn + k0 + lc];
            float4 vb = *(const float4*)&Wa [(size_t)(colBase + r) * Cn + k0 + lc];
            *(uint4*)&As[r][lc] = make_uint4(f2tf(va.x), f2tf(va.y), f2tf(va.z), f2tf(va.w));
            *(uint4*)&Bs[r][lc] = make_uint4(f2tf(vb.x), f2tf(vb.y), f2tf(vb.z), f2tf(vb.w));
        }
        __syncthreads();

#pragma unroll
        for (int kk = 0; kk < 32; kk += 8) {
            int kq = kk + (lane & 3);
            uint32_t af[2][4], bf[8][2];
#pragma unroll
            for (int mi = 0; mi < 2; ++mi) {
                int m = warpM * 32 + mi * 16 + (lane >> 2);
                af[mi][0] = As[m][kq];
                af[mi][1] = As[m + 8][kq];
                af[mi][2] = As[m][kq + 4];
                af[mi][3] = As[m + 8][kq + 4];
            }
#pragma unroll
            for (int ni = 0; ni < 8; ++ni) {
                int n = warpC * 64 + ni * 8 + (lane >> 2);
                bf[ni][0] = Bs[n][kq];
                bf[ni][1] = Bs[n][kq + 4];
            }
#pragma unroll
            for (int mi = 0; mi < 2; ++mi)
#pragma unroll
                for (int ni = 0; ni < 8; ++ni)
                    mma_tf32(acc[mi][ni], af[mi], bf[ni]);
        }
        __syncthreads();
    }

    // Epilogue: tanh(av + ah) . Wd  -> partial per row over this warp's 64 cols
    int slice = blockIdx.x * 2 + warpC;
#pragma unroll
    for (int mi = 0; mi < 2; ++mi) {
#pragma unroll
        for (int h = 0; h < 2; ++h) {
            int rloc = warpM * 32 + mi * 16 + h * 8 + (lane >> 2);
            int grow = rowBase + rloc;
            int bb = grow / Nn - b0;
            float s = 0.f;
#pragma unroll
            for (int ni = 0; ni < 8; ++ni) {
                int cl = warpC * 64 + ni * 8 + 2 * (lane & 3);
                s += fast_tanh(acc[mi][ni][h * 2 + 0] + sAh[bb][cl])     * sWd[cl];
                s += fast_tanh(acc[mi][ni][h * 2 + 1] + sAh[bb][cl + 1]) * sWd[cl + 1];
            }
            s += __shfl_xor_sync(0xffffffffu, s, 1);
            s += __shfl_xor_sync(0xffffffffu, s, 2);
            if ((lane & 3) == 0)
                g_spart[(size_t)slice * Mrows + grow] = s;
        }
    }
}

// ---------------------------------------------------------------------------
// K4: scores = sum(8 partials) + bd; softmax over 49; out[b,c] = sum_n a*w
// grid (4 col-chunks, 256 b), 128 threads
// ---------------------------------------------------------------------------
__global__ __launch_bounds__(128) void softmax_out_kernel(const float* __restrict__ bd,
                                                          float* __restrict__ out) {
    int b   = blockIdx.y;
    int tid = threadIdx.x;
    int c   = blockIdx.x * 128 + tid;
    __shared__ float w[Nn];
    __shared__ float sinv;

    if (tid < Nn) {
        float s = bd[0];
#pragma unroll
        for (int i = 0; i < 8; ++i) s += g_spart[(size_t)i * Mrows + b * Nn + tid];
        w[tid] = s;
    }
    __syncthreads();
    if (tid == 0) {
        float m = -1e30f;
        for (int n = 0; n < Nn; ++n) m = fmaxf(m, w[n]);
        float sum = 0.f;
        for (int n = 0; n < Nn; ++n) { float e = __expf(w[n] - m); w[n] = e; sum += e; }
        sinv = 1.0f / sum;
    }
    __syncthreads();
    float inv = sinv;

    const float* ab = g_a + (size_t)b * Nn * Cn + c;
    float acc = 0.f;
#pragma unroll
    for (int n = 0; n < Nn; ++n) acc += ab[n * Cn] * w[n];
    out[(size_t)b * Cn + c] = acc * inv;
}

// ---------------------------------------------------------------------------
extern "C" void kernel_launch(void* const* d_in, const int* in_sizes, int n_in,
                              void* d_out, int out_size) {
    const float* att_v = (const float*)d_in[0];
    const float* h     = (const float*)d_in[1];
    const float* Wa    = (const float*)d_in[2];
    const float* ba    = (const float*)d_in[3];
    const float* Wh    = (const float*)d_in[4];
    const float* bh    = (const float*)d_in[5];
    const float* Wd    = (const float*)d_in[6];
    const float* bd    = (const float*)d_in[7];
    float* out = (float*)d_out;

    pool_kernel       <<<dim3(16, 256), 256>>>(att_v);
    h2a_kernel        <<<dim3(32, 16),  256>>>(h, Wh, bh, ba);
    gemm_score_kernel <<<dim3(4, 98),   256>>>(Wa, Wd);
    softmax_out_kernel<<<dim3(4, 256),  128>>>(bd, out);
}

// round 4
// speedup vs baseline: 2.6668x; 1.2985x over previous
#include <cuda_runtime.h>
#include <cuda_bf16.h>
#include <cstdint>

// Problem constants
#define Bn   256
#define Cn   512
#define Nn   49          // 7x7 attention positions
#define HWn  196         // 14*14
#define Mrows (Bn*Nn)    // 12544

// Scratch (no allocation allowed)
__device__ float          g_a [Mrows * Cn];   // pooled fp32 (final einsum)
__device__ __nv_bfloat16  g_ab[Mrows * Cn];   // pooled bf16 (GEMM A)
__device__ __nv_bfloat16  g_wb[Cn * Cn];      // Wa bf16 (GEMM B)
__device__ float          g_ah[Bn * Cn];      // h@Wh^T + bh + ba
__device__ float          g_spart[8 * Mrows]; // per (col-tile, col-half) partials

__device__ __forceinline__ float fast_tanh(float x) {
    float y; asm("tanh.approx.f32 %0, %1;" : "=f"(y) : "f"(x)); return y;
}
__device__ __forceinline__ uint32_t smem_u32(const void* p) {
    uint32_t a;
    asm("{ .reg .u64 t; cvta.to.shared.u64 t, %1; cvt.u32.u64 %0, t; }" : "=r"(a) : "l"(p));
    return a;
}
__device__ __forceinline__ void cp16(uint32_t dst, const void* src) {
    asm volatile("cp.async.cg.shared.global [%0], [%1], 16;" :: "r"(dst), "l"(src));
}
__device__ __forceinline__ void mma_bf16(float* d, const uint32_t* a, const uint32_t* b) {
    asm volatile(
        "mma.sync.aligned.m16n8k16.row.col.f32.bf16.bf16.f32 "
        "{%0,%1,%2,%3}, {%4,%5,%6,%7}, {%8,%9}, {%0,%1,%2,%3};"
        : "+f"(d[0]), "+f"(d[1]), "+f"(d[2]), "+f"(d[3])
        : "r"(a[0]), "r"(a[1]), "r"(a[2]), "r"(a[3]), "r"(b[0]), "r"(b[1]));
}

// ---------------------------------------------------------------------------
// K1: 2x2 avg pool -> g_a (fp32) and g_ab (bf16), layout [B*49, C]
// ---------------------------------------------------------------------------
__global__ __launch_bounds__(256) void pool_kernel(const float* __restrict__ att_v) {
    int b  = blockIdx.y;
    int c0 = blockIdx.x * 32;
    __shared__ float pool[32][51];
    const float* base = att_v + ((size_t)b * Cn + c0) * HWn;
    int tid = threadIdx.x;

    for (int idx = tid; idx < 32 * Nn; idx += 256) {
        int cl = idx / Nn, n = idx % Nn;
        int i = n / 7, j = n % 7;
        const float* p = base + cl * HWn + i * 28 + j * 2;
        float2 t = *(const float2*)p;
        float2 u = *(const float2*)(p + 14);
        pool[cl][n] = (t.x + t.y + u.x + u.y) * 0.25f;
    }
    __syncthreads();
    for (int idx = tid; idx < 32 * Nn; idx += 256) {
        int n = idx / 32, cl = idx % 32;
        float v = pool[cl][n];
        size_t o = (size_t)(b * Nn + n) * Cn + c0 + cl;
        g_a[o]  = v;
        g_ab[o] = __float2bfloat16_rn(v);
    }
}

// ---------------------------------------------------------------------------
// K1b: Wa fp32 -> bf16
// ---------------------------------------------------------------------------
__global__ __launch_bounds__(256) void convert_wa_kernel(const float* __restrict__ Wa) {
    int i = (blockIdx.x * 256 + threadIdx.x) * 4;
    float4 v = *(const float4*)(Wa + i);
    __nv_bfloat162 lo(__float2bfloat16_rn(v.x), __float2bfloat16_rn(v.y));
    __nv_bfloat162 hi(__float2bfloat16_rn(v.z), __float2bfloat16_rn(v.w));
    *(__nv_bfloat162*)(g_wb + i)     = lo;
    *(__nv_bfloat162*)(g_wb + i + 2) = hi;
}

// ---------------------------------------------------------------------------
// K2: g_ah[b,d] = h@Wh^T + bh + ba
// ---------------------------------------------------------------------------
__global__ __launch_bounds__(256) void h2a_kernel(const float* __restrict__ h,
                                                  const float* __restrict__ Wh,
                                                  const float* __restrict__ bh,
                                                  const float* __restrict__ ba) {
    __shared__ float sh[16][132];
    __shared__ float sw[16][132];
    int tid = threadIdx.x;
    int tx = tid & 15, ty = tid >> 4;
    int d0 = blockIdx.x * 16, b0 = blockIdx.y * 16;
    float acc = 0.f;

    for (int c0 = 0; c0 < Cn; c0 += 128) {
#pragma unroll
        for (int p = 0; p < 2; ++p) {
            int i = tid + p * 256;
            int r = i >> 5;
            int cc = (i & 31) * 4;
            *(float4*)&sh[r][cc] = *(const float4*)&h [(size_t)(b0 + r) * Cn + c0 + cc];
            *(float4*)&sw[r][cc] = *(const float4*)&Wh[(size_t)(d0 + r) * Cn + c0 + cc];
        }
        __syncthreads();
#pragma unroll
        for (int c = 0; c < 128; ++c) acc += sh[ty][c] * sw[tx][c];
        __syncthreads();
    }
    int d = d0 + tx, b = b0 + ty;
    g_ah[(size_t)b * Cn + d] = acc + bh[d] + ba[d];
}

// ---------------------------------------------------------------------------
// K3: bf16 mma.sync GEMM(M=12544,N=512,K=512) + tanh + dot(Wd) epilogue
// BM=BN=128, BK=32; 8 warps = 4(M) x 2(N); warp tile 32x64 via m16n8k16.
// 2-stage cp.async pipeline. grid (4 col-tiles, 98 row-tiles), 256 threads.
// ---------------------------------------------------------------------------
#define PITCH 40   // bf16 per smem row (80B): conflict-free LDS.32 fragments

__global__ __launch_bounds__(256, 2) void gemm_score_kernel(const float* __restrict__ Wd) {
    __shared__ __align__(16) __nv_bfloat16 As[2][128][PITCH];
    __shared__ __align__(16) __nv_bfloat16 Bs[2][128][PITCH];
    __shared__ float sAh[4][128];
    __shared__ float sWd[128];

    int tid  = threadIdx.x;
    int lane = tid & 31;
    int warp = tid >> 5;
    int warpM = warp & 3;              // 0..3 (32 rows each)
    int warpC = warp >> 2;             // 0..1 (64 cols each)
    int rowBase = blockIdx.y * 128;
    int colBase = blockIdx.x * 128;
    int b0 = rowBase / Nn;

    // stage ah + Wd tiles
    for (int i = tid; i < 4 * 128; i += 256) {
        int bb = i >> 7, c = i & 127;
        int b = b0 + bb;
        sAh[bb][c] = (b < Bn) ? g_ah[(size_t)b * Cn + colBase + c] : 0.f;
    }
    if (tid < 128) sWd[tid] = Wd[colBase + tid];

    // cp.async load decomposition: 1024 16B chunks per stage, 4 per thread
    int row  = tid >> 1;          // shared by the A-chunk pairs below
    // chunk mapping: t in 0..3 -> chunk = tid + t*256; t<2: A, t>=2: B
    const __nv_bfloat16* gA = g_ab + (size_t)rowBase * Cn;
    const __nv_bfloat16* gB = g_wb + (size_t)colBase * Cn;

    auto load_stage = [&](int s, int buf) {
#pragma unroll
        for (int t = 0; t < 4; ++t) {
            int chunk = tid + t * 256;       // 0..1023
            int c2  = chunk & 511;
            int r   = c2 >> 2;
            int cc  = c2 & 3;
            if (chunk < 512) {
                cp16(smem_u32(&As[buf][r][cc * 8]),
                     gA + (size_t)r * Cn + s * 32 + cc * 8);
            } else {
                cp16(smem_u32(&Bs[buf][r][cc * 8]),
                     gB + (size_t)r * Cn + s * 32 + cc * 8);
            }
        }
        asm volatile("cp.async.commit_group;" ::: "memory");
    };

    float acc[2][8][4];
#pragma unroll
    for (int mi = 0; mi < 2; ++mi)
#pragma unroll
        for (int ni = 0; ni < 8; ++ni)
#pragma unroll
            for (int q = 0; q < 4; ++q) acc[mi][ni][q] = 0.f;

    load_stage(0, 0);
    load_stage(1, 1);

    int gid = lane >> 2;          // 0..7
    int kq0 = (lane & 3) * 2;     // 0,2,4,6

#pragma unroll 1
    for (int s = 0; s < 16; ++s) {
        int buf = s & 1;
        if (s < 15) asm volatile("cp.async.wait_group 1;" ::: "memory");
        else        asm volatile("cp.async.wait_group 0;" ::: "memory");
        __syncthreads();

#pragma unroll
        for (int kk = 0; kk < 32; kk += 16) {
            int kq = kk + kq0;
            uint32_t af[2][4], bf[8][2];
#pragma unroll
            for (int mi = 0; mi < 2; ++mi) {
                int m = warpM * 32 + mi * 16 + gid;
                af[mi][0] = *(const uint32_t*)&As[buf][m][kq];
                af[mi][1] = *(const uint32_t*)&As[buf][m + 8][kq];
                af[mi][2] = *(const uint32_t*)&As[buf][m][kq + 8];
                af[mi][3] = *(const uint32_t*)&As[buf][m + 8][kq + 8];
            }
#pragma unroll
            for (int ni = 0; ni < 8; ++ni) {
                int n = warpC * 64 + ni * 8 + gid;
                bf[ni][0] = *(const uint32_t*)&Bs[buf][n][kq];
                bf[ni][1] = *(const uint32_t*)&Bs[buf][n][kq + 8];
            }
#pragma unroll
            for (int mi = 0; mi < 2; ++mi)
#pragma unroll
                for (int ni = 0; ni < 8; ++ni)
                    mma_bf16(acc[mi][ni], af[mi], bf[ni]);
        }
        __syncthreads();
        if (s + 2 < 16) load_stage(s + 2, buf);
    }

    // Epilogue: tanh(av + ah) . Wd -> per-row partial over this warp's 64 cols
    int slice = blockIdx.x * 2 + warpC;
#pragma unroll
    for (int mi = 0; mi < 2; ++mi) {
#pragma unroll
        for (int h = 0; h < 2; ++h) {
            int rloc = warpM * 32 + mi * 16 + h * 8 + gid;
            int grow = rowBase + rloc;
            int bb = grow / Nn - b0;
            float s = 0.f;
#pragma unroll
            for (int ni = 0; ni < 8; ++ni) {
                int cl = warpC * 64 + ni * 8 + kq0;
                s += fast_tanh(acc[mi][ni][h * 2 + 0] + sAh[bb][cl])     * sWd[cl];
                s += fast_tanh(acc[mi][ni][h * 2 + 1] + sAh[bb][cl + 1]) * sWd[cl + 1];
            }
            s += __shfl_xor_sync(0xffffffffu, s, 1);
            s += __shfl_xor_sync(0xffffffffu, s, 2);
            if ((lane & 3) == 0)
                g_spart[(size_t)slice * Mrows + grow] = s;
        }
    }
    (void)row;
}

// ---------------------------------------------------------------------------
// K4: scores = sum(8 partials) + bd; softmax over 49; out[b,c] = sum_n a*w
// ---------------------------------------------------------------------------
__global__ __launch_bounds__(128) void softmax_out_kernel(const float* __restrict__ bd,
                                                          float* __restrict__ out) {
    int b   = blockIdx.y;
    int tid = threadIdx.x;
    int c   = blockIdx.x * 128 + tid;
    __shared__ float w[Nn];
    __shared__ float sinv;

    if (tid < Nn) {
        float s = bd[0];
#pragma unroll
        for (int i = 0; i < 8; ++i) s += g_spart[(size_t)i * Mrows + b * Nn + tid];
        w[tid] = s;
    }
    __syncthreads();
    if (tid == 0) {
        float m = -1e30f;
        for (int n = 0; n < Nn; ++n) m = fmaxf(m, w[n]);
        float sum = 0.f;
        for (int n = 0; n < Nn; ++n) { float e = __expf(w[n] - m); w[n] = e; sum += e; }
        sinv = 1.0f / sum;
    }
    __syncthreads();
    float inv = sinv;

    const float* ab = g_a + (size_t)b * Nn * Cn + c;
    float acc = 0.f;
#pragma unroll
    for (int n = 0; n < Nn; ++n) acc += ab[n * Cn] * w[n];
    out[(size_t)b * Cn + c] = acc * inv;
}

// ---------------------------------------------------------------------------
extern "C" void kernel_launch(void* const* d_in, const int* in_sizes, int n_in,
                              void* d_out, int out_size) {
    const float* att_v = (const float*)d_in[0];
    const float* h     = (const float*)d_in[1];
    const float* Wa    = (const float*)d_in[2];
    const float* ba    = (const float*)d_in[3];
    const float* Wh    = (const float*)d_in[4];
    const float* bh    = (const float*)d_in[5];
    const float* Wd    = (const float*)d_in[6];
    const float* bd    = (const float*)d_in[7];
    float* out = (float*)d_out;

    pool_kernel       <<<dim3(16, 256), 256>>>(att_v);
    convert_wa_kernel <<<256, 256>>>(Wa);
    h2a_kernel        <<<dim3(32, 16),  256>>>(h, Wh, bh, ba);
    gemm_score_kernel <<<dim3(4, 98),   256>>>(Wd);
    softmax_out_kernel<<<dim3(4, 256),  128>>>(bd, out);
}

// round 5
// speedup vs baseline: 2.8186x; 1.0569x over previous
#include <cuda_runtime.h>
#include <cuda_bf16.h>
#include <cstdint>

// Problem constants
#define Bn   256
#define Cn   512
#define Nn   49          // 7x7 attention positions
#define HWn  196         // 14*14
#define Mrows (Bn*Nn)    // 12544

// Scratch (no allocation allowed)
__device__ float          g_a [Mrows * Cn];   // pooled fp32 (final einsum)
__device__ __nv_bfloat16  g_ab[Mrows * Cn];   // pooled bf16 (GEMM A)
__device__ __nv_bfloat16  g_wb[Cn * Cn];      // Wa bf16 (GEMM B)
__device__ float          g_ah[Bn * Cn];      // h@Wh^T + bh + ba
__device__ float          g_spart[8 * Mrows]; // per (col-tile, col-half) partials

__device__ __forceinline__ float fast_tanh(float x) {
    float y; asm("tanh.approx.f32 %0, %1;" : "=f"(y) : "f"(x)); return y;
}
__device__ __forceinline__ uint32_t smem_u32(const void* p) {
    uint32_t a;
    asm("{ .reg .u64 t; cvta.to.shared.u64 t, %1; cvt.u32.u64 %0, t; }" : "=r"(a) : "l"(p));
    return a;
}
__device__ __forceinline__ void cp16(uint32_t dst, const void* src) {
    asm volatile("cp.async.cg.shared.global [%0], [%1], 16;" :: "r"(dst), "l"(src));
}
__device__ __forceinline__ void ldsm4(uint32_t& r0, uint32_t& r1, uint32_t& r2,
                                      uint32_t& r3, uint32_t addr) {
    asm volatile("ldmatrix.sync.aligned.m8n8.x4.shared.b16 {%0,%1,%2,%3}, [%4];"
                 : "=r"(r0), "=r"(r1), "=r"(r2), "=r"(r3) : "r"(addr));
}
__device__ __forceinline__ void mma_bf16(float* d, const uint32_t* a, const uint32_t* b) {
    asm volatile(
        "mma.sync.aligned.m16n8k16.row.col.f32.bf16.bf16.f32 "
        "{%0,%1,%2,%3}, {%4,%5,%6,%7}, {%8,%9}, {%0,%1,%2,%3};"
        : "+f"(d[0]), "+f"(d[1]), "+f"(d[2]), "+f"(d[3])
        : "r"(a[0]), "r"(a[1]), "r"(a[2]), "r"(a[3]), "r"(b[0]), "r"(b[1]));
}

// ---------------------------------------------------------------------------
// K1: 2x2 avg pool -> g_a (fp32) and g_ab (bf16), layout [B*49, C]
// ---------------------------------------------------------------------------
__global__ __launch_bounds__(256) void pool_kernel(const float* __restrict__ att_v) {
    int b  = blockIdx.y;
    int c0 = blockIdx.x * 32;
    __shared__ float pool[32][51];
    const float* base = att_v + ((size_t)b * Cn + c0) * HWn;
    int tid = threadIdx.x;

    for (int idx = tid; idx < 32 * Nn; idx += 256) {
        int cl = idx / Nn, n = idx % Nn;
        int i = n / 7, j = n % 7;
        const float* p = base + cl * HWn + i * 28 + j * 2;
        float2 t = *(const float2*)p;
        float2 u = *(const float2*)(p + 14);
        pool[cl][n] = (t.x + t.y + u.x + u.y) * 0.25f;
    }
    __syncthreads();
    for (int idx = tid; idx < 32 * Nn; idx += 256) {
        int n = idx / 32, cl = idx % 32;
        float v = pool[cl][n];
        size_t o = (size_t)(b * Nn + n) * Cn + c0 + cl;
        g_a[o]  = v;
        g_ab[o] = __float2bfloat16_rn(v);
    }
}

// ---------------------------------------------------------------------------
// K1b: Wa fp32 -> bf16
// ---------------------------------------------------------------------------
__global__ __launch_bounds__(256) void convert_wa_kernel(const float* __restrict__ Wa) {
    int i = (blockIdx.x * 256 + threadIdx.x) * 4;
    float4 v = *(const float4*)(Wa + i);
    __nv_bfloat162 lo(__float2bfloat16_rn(v.x), __float2bfloat16_rn(v.y));
    __nv_bfloat162 hi(__float2bfloat16_rn(v.z), __float2bfloat16_rn(v.w));
    *(__nv_bfloat162*)(g_wb + i)     = lo;
    *(__nv_bfloat162*)(g_wb + i + 2) = hi;
}

// ---------------------------------------------------------------------------
// K2: g_ah[b,d] = h@Wh^T + bh + ba
// ---------------------------------------------------------------------------
__global__ __launch_bounds__(256) void h2a_kernel(const float* __restrict__ h,
                                                  const float* __restrict__ Wh,
                                                  const float* __restrict__ bh,
                                                  const float* __restrict__ ba) {
    __shared__ float sh[16][132];
    __shared__ float sw[16][132];
    int tid = threadIdx.x;
    int tx = tid & 15, ty = tid >> 4;
    int d0 = blockIdx.x * 16, b0 = blockIdx.y * 16;
    float acc = 0.f;

    for (int c0 = 0; c0 < Cn; c0 += 128) {
#pragma unroll
        for (int p = 0; p < 2; ++p) {
            int i = tid + p * 256;
            int r = i >> 5;
            int cc = (i & 31) * 4;
            *(float4*)&sh[r][cc] = *(const float4*)&h [(size_t)(b0 + r) * Cn + c0 + cc];
            *(float4*)&sw[r][cc] = *(const float4*)&Wh[(size_t)(d0 + r) * Cn + c0 + cc];
        }
        __syncthreads();
#pragma unroll
        for (int c = 0; c < 128; ++c) acc += sh[ty][c] * sw[tx][c];
        __syncthreads();
    }
    int d = d0 + tx, b = b0 + ty;
    g_ah[(size_t)b * Cn + d] = acc + bh[d] + ba[d];
}

// ---------------------------------------------------------------------------
// K3: bf16 mma.sync GEMM + tanh + dot(Wd). ldmatrix fragments, 4-stage
// cp.async pipeline, one __syncthreads per stage.
// BM=BN=128, BK=32; 8 warps = 4(M) x 2(N). grid (4, 98), 256 threads.
// ---------------------------------------------------------------------------
#define PITCHB   80          // bytes per smem row (40 bf16)
#define STG_MAT  10240       // 128 rows * 80B, per matrix per stage
#define STG_BOTH 20480       // A+B per stage
#define OFF_AH   81920       // 4 stages * 20480
#define OFF_WD   84480       // OFF_AH + 4*128*4 + pad
#define SMEM_SZ  84992

__global__ __launch_bounds__(256, 2) void gemm_score_kernel(const float* __restrict__ Wd) {
    extern __shared__ __align__(16) char smem[];
    uint32_t sb = smem_u32(smem);
    float* sAh = (float*)(smem + OFF_AH);
    float* sWd = (float*)(smem + OFF_WD);

    int tid  = threadIdx.x;
    int lane = tid & 31;
    int warp = tid >> 5;
    int warpM = warp & 3;
    int warpC = warp >> 2;
    int rowBase = blockIdx.y * 128;
    int colBase = blockIdx.x * 128;
    int b0 = rowBase / Nn;

    for (int i = tid; i < 4 * 128; i += 256) {
        int bb = i >> 7, c = i & 127;
        int b = b0 + bb;
        sAh[i] = (b < Bn) ? g_ah[(size_t)b * Cn + colBase + c] : 0.f;
    }
    if (tid < 128) sWd[tid] = Wd[colBase + tid];

    const __nv_bfloat16* gA = g_ab + (size_t)rowBase * Cn;
    const __nv_bfloat16* gB = g_wb + (size_t)colBase * Cn;

    // cp.async decomposition: 4 chunks/thread/stage (512 A + 512 B 16B chunks)
    int ld_r  = (tid & 511) >> 2;    // unused pattern base; per-chunk below
    auto load_stage = [&](int s, int buf) {
        uint32_t base = sb + buf * STG_BOTH;
#pragma unroll
        for (int t = 0; t < 4; ++t) {
            int chunk = tid + t * 256;
            int c2 = chunk & 511;
            int r  = c2 >> 2;
            int cc = c2 & 3;
            if (chunk < 512)
                cp16(base + r * PITCHB + cc * 16, gA + (size_t)r * Cn + s * 32 + cc * 8);
            else
                cp16(base + STG_MAT + r * PITCHB + cc * 16, gB + (size_t)r * Cn + s * 32 + cc * 8);
        }
        asm volatile("cp.async.commit_group;" ::: "memory");
    };

    float acc[2][8][4];
#pragma unroll
    for (int mi = 0; mi < 2; ++mi)
#pragma unroll
        for (int ni = 0; ni < 8; ++ni)
#pragma unroll
            for (int q = 0; q < 4; ++q) acc[mi][ni][q] = 0.f;

    // ldmatrix per-lane base addresses (bytes)
    uint32_t aBase = sb + (uint32_t)(warpM * 32 + (lane & 15)) * PITCHB + ((lane >> 4) << 4);
    uint32_t bBase = sb + STG_MAT +
                     (uint32_t)(warpC * 64 + ((lane >> 4) << 3) + (lane & 7)) * PITCHB +
                     (((lane >> 3) & 1) << 4);

    load_stage(0, 0);
    load_stage(1, 1);
    load_stage(2, 2);

#pragma unroll 1
    for (int s = 0; s < 16; ++s) {
        int buf = s & 3;
        if (s < 14)       asm volatile("cp.async.wait_group 2;" ::: "memory");
        else if (s == 14) asm volatile("cp.async.wait_group 1;" ::: "memory");
        else              asm volatile("cp.async.wait_group 0;" ::: "memory");
        __syncthreads();

        uint32_t aS = aBase + buf * STG_BOTH;
        uint32_t bS = bBase + buf * STG_BOTH;
#pragma unroll
        for (int kk = 0; kk < 2; ++kk) {           // two k16 halves of BK=32
            uint32_t kb = kk * 32;                  // 16 bf16 = 32B
            uint32_t af[2][4], bf[8][2];
#pragma unroll
            for (int mi = 0; mi < 2; ++mi)
                ldsm4(af[mi][0], af[mi][1], af[mi][2], af[mi][3],
                      aS + mi * (16 * PITCHB) + kb);
#pragma unroll
            for (int np = 0; np < 4; ++np)
                ldsm4(bf[2 * np][0], bf[2 * np][1], bf[2 * np + 1][0], bf[2 * np + 1][1],
                      bS + np * (16 * PITCHB) + kb);
#pragma unroll
            for (int mi = 0; mi < 2; ++mi)
#pragma unroll
                for (int ni = 0; ni < 8; ++ni)
                    mma_bf16(acc[mi][ni], af[mi], bf[ni]);
        }
        if (s + 3 < 16) load_stage(s + 3, (s + 3) & 3);
    }

    // Epilogue: tanh(av + ah) . Wd -> per-row partial over this warp's 64 cols
    int gid = lane >> 2;
    int kq0 = (lane & 3) * 2;
    int slice = blockIdx.x * 2 + warpC;
#pragma unroll
    for (int mi = 0; mi < 2; ++mi) {
#pragma unroll
        for (int hh = 0; hh < 2; ++hh) {
            int rloc = warpM * 32 + mi * 16 + hh * 8 + gid;
            int grow = rowBase + rloc;
            int bb = grow / Nn - b0;
            float s = 0.f;
#pragma unroll
            for (int ni = 0; ni < 8; ++ni) {
                int cl = warpC * 64 + ni * 8 + kq0;
                s += fast_tanh(acc[mi][ni][hh * 2 + 0] + sAh[bb * 128 + cl])     * sWd[cl];
                s += fast_tanh(acc[mi][ni][hh * 2 + 1] + sAh[bb * 128 + cl + 1]) * sWd[cl + 1];
            }
            s += __shfl_xor_sync(0xffffffffu, s, 1);
            s += __shfl_xor_sync(0xffffffffu, s, 2);
            if ((lane & 3) == 0)
                g_spart[(size_t)slice * Mrows + grow] = s;
        }
    }
    (void)ld_r;
}

// ---------------------------------------------------------------------------
// K4: scores = sum(8 partials) + bd; softmax over 49; out[b,c] = sum_n a*w
// one block per batch, 256 threads, float2 per thread
// ---------------------------------------------------------------------------
__global__ __launch_bounds__(256) void softmax_out_kernel(const float* __restrict__ bd,
                                                          float* __restrict__ out) {
    int b   = blockIdx.x;
    int tid = threadIdx.x;
    __shared__ float w[Nn];
    __shared__ float sinv;

    if (tid < Nn) {
        float s = bd[0];
#pragma unroll
        for (int i = 0; i < 8; ++i) s += g_spart[(size_t)i * Mrows + b * Nn + tid];
        w[tid] = s;
    }
    __syncthreads();
    if (tid == 0) {
        float m = -1e30f;
        for (int n = 0; n < Nn; ++n) m = fmaxf(m, w[n]);
        float sum = 0.f;
        for (int n = 0; n < Nn; ++n) { float e = __expf(w[n] - m); w[n] = e; sum += e; }
        sinv = 1.0f / sum;
    }
    __syncthreads();
    float inv = sinv;

    int c = tid * 2;
    const float* ab = g_a + (size_t)b * Nn * Cn + c;
    float ax = 0.f, ay = 0.f;
#pragma unroll 7
    for (int n = 0; n < Nn; ++n) {
        float2 v = *(const float2*)(ab + (size_t)n * Cn);
        float wn = w[n];
        ax += v.x * wn; ay += v.y * wn;
    }
    float2 o = make_float2(ax * inv, ay * inv);
    *(float2*)(out + (size_t)b * Cn + c) = o;
}

// ---------------------------------------------------------------------------
extern "C" void kernel_launch(void* const* d_in, const int* in_sizes, int n_in,
                              void* d_out, int out_size) {
    const float* att_v = (const float*)d_in[0];
    const float* h     = (const float*)d_in[1];
    const float* Wa    = (const float*)d_in[2];
    const float* ba    = (const float*)d_in[3];
    const float* Wh    = (const float*)d_in[4];
    const float* bh    = (const float*)d_in[5];
    const float* Wd    = (const float*)d_in[6];
    const float* bd    = (const float*)d_in[7];
    float* out = (float*)d_out;

    static bool attr_set = false;
    if (!attr_set) {
        cudaFuncSetAttribute(gemm_score_kernel,
                             cudaFuncAttributeMaxDynamicSharedMemorySize, SMEM_SZ);
        attr_set = true;
    }

    pool_kernel       <<<dim3(16, 256), 256>>>(att_v);
    convert_wa_kernel <<<256, 256>>>(Wa);
    h2a_kernel        <<<dim3(32, 16),  256>>>(h, Wh, bh, ba);
    gemm_score_kernel <<<dim3(4, 98),   256, SMEM_SZ>>>(Wd);
    softmax_out_kernel<<<256, 256>>>(bd, out);
}